// round 10
// baseline (speedup 1.0000x reference)
#include <cuda_runtime.h>
#include <cuda_fp16.h>

// ---------------------------------------------------------------- constants
#define A_TOT 900
#define P_PTS 13
#define NCAMS 6
#define CDIM  256
#define NPN   (P_PTS * NCAMS)        // 78 (p-major, cam inner)

#define W0 176
#define H0 64
#define W1 88
#define H1 32
#define W2 44
#define H2 16
#define W3 22
#define H3 8

// fp16 scratch for ALL levels, uint2 = 4 halves. Per pixel: 256ch = 64 uint2.
#define L0_U2 4325376                 // 6*64*176 px * 64
#define L1_U2 1081344                 // 6*32*88  px * 64
#define L2_U2 270336                  // 6*16*44  px * 64
#define L3_U2 67584                   // 6*8*22   px * 64
#define L1_BASE L0_U2
#define L2_BASE (L0_U2 + L1_U2)
#define L3_BASE (L0_U2 + L1_U2 + L2_U2)
#define FMH_U2  (L0_U2 + L1_U2 + L2_U2 + L3_U2)   // 5744640

// prep: 4 uint2 per thread
#define CONV_THREADS (FMH_U2 / 4)          // 1436160
#define CONV_BLKS    (CONV_THREADS / 256)  // 5610 exactly
#define PREP_BLKS    (CONV_BLKS + A_TOT)

__device__ float g_acc[A_TOT * CDIM];
__device__ uint2 g_fmh[FMH_U2];

// ---------------------------------------------------------------------------
// K1: prep. Convert fm0..fm3 -> fp16 (4 float4 loads per thread, MLP=4);
// init out = [bias | instance]; zero g_acc.
// ---------------------------------------------------------------------------
__global__ void __launch_bounds__(256) prep_kernel(
    const float* __restrict__ fm0, const float* __restrict__ fm1,
    const float* __restrict__ fm2, const float* __restrict__ fm3,
    const float* __restrict__ inst, const float* __restrict__ bproj,
    float* __restrict__ out)
{
    const int b = blockIdx.x;
    const int t = threadIdx.x;

    if (b < CONV_BLKS) {
        int base = (b * 256 + t) * 4;      // uint2 index, 4 consecutive
        // all level sizes are multiples of 4: 4-group never straddles levels
        const float* src;
        int off;
        if (base < L1_BASE)      { src = fm0; off = base; }
        else if (base < L2_BASE) { src = fm1; off = base - L1_BASE; }
        else if (base < L3_BASE) { src = fm2; off = base - L2_BASE; }
        else                     { src = fm3; off = base - L3_BASE; }
        float4 f[4];
        #pragma unroll
        for (int j = 0; j < 4; ++j) f[j] = __ldg(((const float4*)src) + off + j);
        #pragma unroll
        for (int j = 0; j < 4; ++j) {
            __half2 h0 = __floats2half2_rn(f[j].x, f[j].y);
            __half2 h1 = __floats2half2_rn(f[j].z, f[j].w);
            uint2 u;
            u.x = *reinterpret_cast<unsigned*>(&h0);
            u.y = *reinterpret_cast<unsigned*>(&h1);
            g_fmh[base + j] = u;
        }
    } else {
        int a = b - CONV_BLKS;
        out[(size_t)a * 512 + t]       = __ldg(bproj + t);
        out[(size_t)a * 512 + 256 + t] = __ldg(inst + (size_t)a * 256 + t);
        g_acc[(size_t)a * 256 + t] = 0.f;
    }
}

// ---------------------------------------------------------------------------
// K2: daf — perfectly balanced role blocks: role = level, grid = 4*900.
// Every block gathers 78 samples * 4 corners * 512B = 143.6 MB/role total.
// Uniform fp16 gather from g_fmh; results atomicAdd into g_acc.
// ---------------------------------------------------------------------------
__global__ void __launch_bounds__(64) daf_kernel(
    const float* __restrict__ pts, const float* __restrict__ wts)
{
    __shared__ int4   soff[NPN];
    __shared__ float4 swt[NPN];
    __shared__ float  swg[NPN * 8];

    const int b = blockIdx.x;
    const int a = b % A_TOT;
    const int level = b / A_TOT;
    const int t = threadIdx.x;

    // stage group weights for this level: [s][8], via float4 pairs
    {
        const float4* wsrc = (const float4*)wts;
        #pragma unroll
        for (int i = t; i < NPN * 2; i += 64) {
            int s = i >> 1, h = i & 1;
            ((float4*)swg)[i] =
                __ldg(wsrc + (size_t)(a * NPN + s) * 8 + level * 2 + h);
        }
    }

    // per-sample bilinear precompute
    {
        const int Ws[4] = {W0, W1, W2, W3};
        const int Hs[4] = {H0, H1, H2, H3};
        const int Bs[4] = {0, L1_BASE, L2_BASE, L3_BASE};
        const int W = Ws[level], H = Hs[level], base = Bs[level];
        const float* pbase = pts + (size_t)a * NPN * 2;
        for (int s = t; s < NPN; s += 64) {
            int n = s % NCAMS;
            float px = __ldg(pbase + s * 2 + 0);
            float py = __ldg(pbase + s * 2 + 1);
            float x = px * (float)W - 0.5f;
            float y = py * (float)H - 0.5f;
            float xf = floorf(x), yf = floorf(y);
            float fx = x - xf, fy = y - yf;
            int x0 = (int)xf, y0 = (int)yf;
            int x1 = x0 + 1, y1 = y0 + 1;
            bool vx0 = (x0 >= 0) & (x0 < W);
            bool vx1 = (x1 >= 0) & (x1 < W);
            bool vy0 = (y0 >= 0) & (y0 < H);
            bool vy1 = (y1 >= 0) & (y1 < H);
            int xc0 = min(max(x0, 0), W - 1);
            int xc1 = min(max(x1, 0), W - 1);
            int yc0 = min(max(y0, 0), H - 1);
            int yc1 = min(max(y1, 0), H - 1);
            int nb = n * H;
            int4 o;   // uint2 units; 64 per pixel
            o.x = base + ((nb + yc0) * W + xc0) * 64;
            o.y = base + ((nb + yc0) * W + xc1) * 64;
            o.z = base + ((nb + yc1) * W + xc0) * 64;
            o.w = base + ((nb + yc1) * W + xc1) * 64;
            soff[s] = o;
            float4 w;
            w.x = (vx0 && vy0) ? (1.f - fx) * (1.f - fy) : 0.f;
            w.y = (vx1 && vy0) ? fx * (1.f - fy) : 0.f;
            w.z = (vx0 && vy1) ? (1.f - fx) * fy : 0.f;
            w.w = (vx1 && vy1) ? fx * fy : 0.f;
            swt[s] = w;
        }
    }
    __syncthreads();

    const int g = t >> 3;
    const uint2* const fh = g_fmh + t;
    float4 acc = make_float4(0.f, 0.f, 0.f, 0.f);

    #pragma unroll 2
    for (int s = 0; s < NPN; ++s) {
        int4 o = soff[s];
        float4 w = swt[s];
        float gw = swg[s * 8 + g];
        uint2 u00 = __ldg(fh + o.x);
        uint2 u10 = __ldg(fh + o.y);
        uint2 u01 = __ldg(fh + o.z);
        uint2 u11 = __ldg(fh + o.w);
        float wx = w.x * gw, wy = w.y * gw, wz = w.z * gw, ww = w.w * gw;
        float2 a0, a1;
        a0 = __half22float2(*reinterpret_cast<__half2*>(&u00.x));
        a1 = __half22float2(*reinterpret_cast<__half2*>(&u00.y));
        acc.x += a0.x * wx; acc.y += a0.y * wx; acc.z += a1.x * wx; acc.w += a1.y * wx;
        a0 = __half22float2(*reinterpret_cast<__half2*>(&u10.x));
        a1 = __half22float2(*reinterpret_cast<__half2*>(&u10.y));
        acc.x += a0.x * wy; acc.y += a0.y * wy; acc.z += a1.x * wy; acc.w += a1.y * wy;
        a0 = __half22float2(*reinterpret_cast<__half2*>(&u01.x));
        a1 = __half22float2(*reinterpret_cast<__half2*>(&u01.y));
        acc.x += a0.x * wz; acc.y += a0.y * wz; acc.z += a1.x * wz; acc.w += a1.y * wz;
        a0 = __half22float2(*reinterpret_cast<__half2*>(&u11.x));
        a1 = __half22float2(*reinterpret_cast<__half2*>(&u11.y));
        acc.x += a0.x * ww; acc.y += a0.y * ww; acc.z += a1.x * ww; acc.w += a1.y * ww;
    }

    float* dst = g_acc + (size_t)a * CDIM + t * 4;
    atomicAdd(dst + 0, acc.x);
    atomicAdd(dst + 1, acc.y);
    atomicAdd(dst + 2, acc.z);
    atomicAdd(dst + 3, acc.w);
}

// ---------------------------------------------------------------------------
// K3: proj — 8 K-chunks of 32, 150 anchor-groups of 6 -> 1200 blocks.
// atomicAdd into out (pre-initialized with bias by prep).
// ---------------------------------------------------------------------------
#define APB 6
__global__ void __launch_bounds__(256) proj_kernel(
    const float* __restrict__ wproj, float* __restrict__ out)
{
    __shared__ float sacc[APB][32];
    const int b = blockIdx.x;
    const int kq = b & 7;
    const int a0 = (b >> 3) * APB;
    const int k0 = kq * 32;
    const int c = threadIdx.x;

    if (c < APB * 32) {
        int ai = c >> 5, kk = c & 31;
        sacc[ai][kk] = g_acc[(size_t)(a0 + ai) * CDIM + k0 + kk];
    }
    __syncthreads();

    float r[APB];
    #pragma unroll
    for (int a = 0; a < APB; ++a) r[a] = 0.f;

    #pragma unroll 8
    for (int kk = 0; kk < 32; ++kk) {
        float wv = __ldg(wproj + (size_t)(k0 + kk) * CDIM + c);
        #pragma unroll
        for (int a = 0; a < APB; ++a) r[a] += sacc[a][kk] * wv;
    }

    #pragma unroll
    for (int a = 0; a < APB; ++a)
        atomicAdd(out + (size_t)(a0 + a) * 512 + c, r[a]);
}

// ---------------------------------------------------------------------------
extern "C" void kernel_launch(void* const* d_in, const int* in_sizes, int n_in,
                              void* d_out, int out_size)
{
    const float* fm0   = (const float*)d_in[0];
    const float* fm1   = (const float*)d_in[1];
    const float* fm2   = (const float*)d_in[2];
    const float* fm3   = (const float*)d_in[3];
    const float* pts   = (const float*)d_in[4];
    const float* wts   = (const float*)d_in[5];
    const float* inst  = (const float*)d_in[6];
    const float* wproj = (const float*)d_in[7];
    const float* bproj = (const float*)d_in[8];
    float* out = (float*)d_out;

    prep_kernel<<<PREP_BLKS, 256>>>(fm0, fm1, fm2, fm3, inst, bproj, out);
    daf_kernel<<<4 * A_TOT, 64>>>(pts, wts);
    proj_kernel<<<(A_TOT / APB) * 8, 256>>>(wproj, out);
}